// round 6
// baseline (speedup 1.0000x reference)
#include <cuda_runtime.h>
#include <math.h>

#define NN 4
#define MM 1128
#define LL 512
#define NF 13
#define NEG_BIG 100000.0f
#define JOBS (2 * NN * MM)      // 9024 (bm, side) tiles
#define TILE  (LL * NF)         // 6656 floats per tile
#define TILE4 (TILE / 4)        // 1664 float4s
#define POOL_GRID 592           // 4 CTAs per SM on 148 SMs

// H vectors per job: g_H[(bm*2 + side)*NF + i]
__device__ __align__(16) float g_H[JOBS * NF];
// d = ||H1-H2||^2, shape [N, M]
__device__ __align__(16) float g_d[NN * MM];

// ---------------- cp.async helpers (LDGSTS) ----------------
__device__ __forceinline__ void cp_async16(void* sdst, const void* gsrc) {
    unsigned int s = (unsigned int)__cvta_generic_to_shared(sdst);
    asm volatile("cp.async.cg.shared.global [%0], [%1], 16;" :: "r"(s), "l"(gsrc) : "memory");
}
__device__ __forceinline__ void cp_commit() {
    asm volatile("cp.async.commit_group;" ::: "memory");
}
template <int N>
__device__ __forceinline__ void cp_wait() {
    asm volatile("cp.async.wait_group %0;" :: "n"(N) : "memory");
}

// ---------------------------------------------------------------------------
// Kernel 1: persistent double-buffered pooling.
// Each job = one (bm, side) tile: load 512x13 X into smem, quadratic-form
// scores, masked softmax over L, weighted sum -> H[13] -> g_H.
// ---------------------------------------------------------------------------
__global__ __launch_bounds__(256, 4) void pool_kernel(
    const float* __restrict__ X1, const float* __restrict__ X2,
    const float* __restrict__ M1, const float* __restrict__ M2,
    const float* __restrict__ attn_w)
{
    extern __shared__ __align__(16) float dynbuf[];   // 2 * TILE floats
    __shared__ float As[NF * NF];
    __shared__ float red[8 * NF];
    __shared__ float sred[16];

    const int tid  = threadIdx.x;
    const int warp = tid >> 5;
    const int lane = tid & 31;

    if (tid < NF * NF) {
        int i = tid / NF, j = tid % NF;
        As[i * NF + j] = attn_w[j * NF + i];   // A = attn_w^T
    }

    float* bufs[2] = { dynbuf, dynbuf + TILE };

    auto xptr = [&](int job) -> const float* {
        const float* X = (job & 1) ? X2 : X1;
        return X + (size_t)(job >> 1) * TILE;
    };
    auto mval = [&](int job, int l) -> float {
        const float* Mk = (job & 1) ? M2 : M1;
        return Mk[(size_t)(job >> 1) * TILE + (size_t)l * NF];
    };
    auto issue_tile = [&](int job, float* buf) {
        const float4* src = (const float4*)xptr(job);
        float4* dst = (float4*)buf;
        #pragma unroll
        for (int k = tid; k < TILE4; k += 256) cp_async16(dst + k, src + k);
        cp_commit();
    };

    int job = blockIdx.x;                      // grid 592 < 9024, always valid
    issue_tile(job, bufs[0]);
    float m0 = mval(job, tid);
    float m1 = mval(job, tid + 256);
    int cur = 0;

    while (true) {
        const int nxt = job + gridDim.x;
        const bool hn = (nxt < JOBS);
        float nm0 = 0.f, nm1 = 0.f;
        if (hn) {
            issue_tile(nxt, bufs[cur ^ 1]);    // prefetch next job's tile
            nm0 = mval(nxt, tid);
            nm1 = mval(nxt, tid + 256);
        }
        if (hn) cp_wait<1>(); else cp_wait<0>();
        __syncthreads();                        // tile (and As on first iter) ready

        const float* Xs = bufs[cur];

        // --- scores + mask, 2 positions per thread ---
        float logit[2];
        #pragma unroll
        for (int p = 0; p < 2; ++p) {
            const float* xr = &Xs[(tid + p * 256) * NF];
            float s = 0.0f;
            #pragma unroll
            for (int i = 0; i < NF; ++i) {
                float y = 0.0f;
                #pragma unroll
                for (int j = 0; j < NF; ++j) y += As[i * NF + j] * xr[j];
                s += xr[i] * y;
            }
            const float mm = (p == 0) ? m0 : m1;
            logit[p] = tanhf(s) + (mm - 1.0f) * NEG_BIG;
        }

        // --- block max over 512 logits ---
        float mx = fmaxf(logit[0], logit[1]);
        #pragma unroll
        for (int o = 16; o; o >>= 1) mx = fmaxf(mx, __shfl_xor_sync(0xffffffffu, mx, o));
        if (lane == 0) sred[warp] = mx;
        __syncthreads();
        float bmax = sred[0];
        #pragma unroll
        for (int w = 1; w < 8; ++w) bmax = fmaxf(bmax, sred[w]);

        // --- exp + block sum ---
        const float e0 = __expf(logit[0] - bmax);
        const float e1 = __expf(logit[1] - bmax);
        float sum = e0 + e1;
        #pragma unroll
        for (int o = 16; o; o >>= 1) sum += __shfl_xor_sync(0xffffffffu, sum, o);
        if (lane == 0) sred[8 + warp] = sum;
        __syncthreads();
        float bsum = 0.0f;
        #pragma unroll
        for (int w = 0; w < 8; ++w) bsum += sred[8 + w];
        const float inv = 1.0f / bsum;
        const float w0 = e0 * inv, w1 = e1 * inv;

        // --- weighted sum H = sum_l W_l x_l ---
        float hpart[NF];
        {
            const float* x0 = &Xs[(tid)       * NF];
            const float* x1 = &Xs[(tid + 256) * NF];
            #pragma unroll
            for (int i = 0; i < NF; ++i) hpart[i] = w0 * x0[i] + w1 * x1[i];
        }
        #pragma unroll
        for (int i = 0; i < NF; ++i) {
            float v = hpart[i];
            #pragma unroll
            for (int o = 16; o; o >>= 1) v += __shfl_xor_sync(0xffffffffu, v, o);
            if (lane == 0) red[warp * NF + i] = v;
        }
        __syncthreads();                        // (e): all Xs/red reads done
        if (tid < NF) {
            float h = 0.0f;
            #pragma unroll
            for (int w = 0; w < 8; ++w) h += red[w * NF + tid];
            g_H[(size_t)job * NF + tid] = h;
        }

        if (!hn) break;
        job = nxt; cur ^= 1; m0 = nm0; m1 = nm1;
    }
}

// ---------------------------------------------------------------------------
// Kernel 2: d[bm] = ||H1 - H2||^2   (g_H is L2-resident)
// ---------------------------------------------------------------------------
__global__ __launch_bounds__(256) void d_kernel()
{
    const int bm = blockIdx.x * 256 + threadIdx.x;
    if (bm < NN * MM) {
        const float* h = g_H + (size_t)bm * 2 * NF;   // H1 then H2, adjacent
        float d = 0.0f;
        #pragma unroll
        for (int i = 0; i < NF; ++i) {
            const float t = h[i] - h[NF + i];
            d += t * t;
        }
        g_d[bm] = d;
    }
}

// ---------------------------------------------------------------------------
// Kernel 3: out[n,i] = sum_j d[n,j] * layer_w[i,j] + layer_b[i]
// grid = 1128 blocks (one column each), 128 threads, float4 loads.
// ---------------------------------------------------------------------------
__global__ __launch_bounds__(128) void fc_kernel(
    const float* __restrict__ layer_w,
    const float* __restrict__ layer_b,
    float* __restrict__ out)
{
    const int i    = blockIdx.x;
    const int tid  = threadIdx.x;
    const int warp = tid >> 5;
    const int lane = tid & 31;

    const float4* wr = (const float4*)(layer_w + (size_t)i * MM);
    const float4* d0 = (const float4*)(g_d);
    const float4* d1 = (const float4*)(g_d + MM);
    const float4* d2 = (const float4*)(g_d + 2 * MM);
    const float4* d3 = (const float4*)(g_d + 3 * MM);

    float a0 = 0.f, a1 = 0.f, a2 = 0.f, a3 = 0.f;
    for (int j = tid; j < MM / 4; j += 128) {
        const float4 w = wr[j];
        float4 v;
        v = d0[j]; a0 += w.x * v.x + w.y * v.y + w.z * v.z + w.w * v.w;
        v = d1[j]; a1 += w.x * v.x + w.y * v.y + w.z * v.z + w.w * v.w;
        v = d2[j]; a2 += w.x * v.x + w.y * v.y + w.z * v.z + w.w * v.w;
        v = d3[j]; a3 += w.x * v.x + w.y * v.y + w.z * v.z + w.w * v.w;
    }
    #pragma unroll
    for (int o = 16; o; o >>= 1) {
        a0 += __shfl_xor_sync(0xffffffffu, a0, o);
        a1 += __shfl_xor_sync(0xffffffffu, a1, o);
        a2 += __shfl_xor_sync(0xffffffffu, a2, o);
        a3 += __shfl_xor_sync(0xffffffffu, a3, o);
    }
    __shared__ float r[4][NN];
    if (lane == 0) { r[warp][0] = a0; r[warp][1] = a1; r[warp][2] = a2; r[warp][3] = a3; }
    __syncthreads();
    if (tid == 0) {
        const float b = layer_b[i];
        #pragma unroll
        for (int n = 0; n < NN; ++n)
            out[n * MM + i] = r[0][n] + r[1][n] + r[2][n] + r[3][n] + b;
    }
}

extern "C" void kernel_launch(void* const* d_in, const int* in_sizes, int n_in,
                              void* d_out, int out_size)
{
    const float* X1      = (const float*)d_in[0];
    const float* X2      = (const float*)d_in[1];
    const float* M1      = (const float*)d_in[2];
    const float* M2      = (const float*)d_in[3];
    const float* attn_w  = (const float*)d_in[4];
    const float* layer_w = (const float*)d_in[5];
    const float* layer_b = (const float*)d_in[6];
    float* out = (float*)d_out;

    const int dyn_smem = 2 * TILE * sizeof(float);   // 53248 B
    cudaFuncSetAttribute(pool_kernel,
                         cudaFuncAttributeMaxDynamicSharedMemorySize, dyn_smem);

    pool_kernel<<<POOL_GRID, 256, dyn_smem>>>(X1, X2, M1, M2, attn_w);
    d_kernel<<<(NN * MM + 255) / 256, 256>>>();
    fc_kernel<<<MM, 128>>>(layer_w, layer_b, out);
}

// round 7
// speedup vs baseline: 5.5985x; 5.5985x over previous
#include <cuda_runtime.h>
#include <math.h>

#define NN 4
#define MM 1128
#define LL 512
#define NF 13
#define NEG_BIG 100000.0f
#define HALF (NN * MM)          // 4512 tiles per side
#define JOBS (2 * HALF)         // 9024
#define TILE  (LL * NF)         // 6656 floats per tile
#define TILE4 (TILE / 4)        // 1664 float4s

// H vectors: g_H[job*NF + i]; job<HALF -> H1[bm], job>=HALF -> H2[bm]
__device__ __align__(16) float g_H[JOBS * NF];
// d = ||H1-H2||^2, shape [N, M]
__device__ __align__(16) float g_d[NN * MM];

// ---------------------------------------------------------------------------
// Kernel 1: one CTA per (tile, side). Load 512x13 X into smem (front-batched
// LDG.128), quadratic-form scores via symmetrized A, masked softmax (no max
// subtraction needed: tanh-bounded logits), weighted sum -> H[13].
// ---------------------------------------------------------------------------
__global__ __launch_bounds__(256) void pool_kernel(
    const float* __restrict__ X1, const float* __restrict__ X2,
    const float* __restrict__ M1, const float* __restrict__ M2,
    const float* __restrict__ attn_w)
{
    __shared__ __align__(16) float Xs[TILE];
    __shared__ float Ss[NF * NF];   // diag: A_ii ; off-diag: A_ij + A_ji
    __shared__ float red[8 * NF];
    __shared__ float sred[8];

    const int tid  = threadIdx.x;
    const int warp = tid >> 5;
    const int lane = tid & 31;
    const int job  = blockIdx.x;

    const float* Xb;
    const float* Mb;
    if (job < HALF) {
        Xb = X1 + (size_t)job * TILE;
        Mb = M1 + (size_t)job * TILE;
    } else {
        Xb = X2 + (size_t)(job - HALF) * TILE;
        Mb = M2 + (size_t)(job - HALF) * TILE;
    }

    // front-batch: mask scalars + whole tile into registers
    const float m0 = Mb[(size_t)tid * NF];
    const float m1 = Mb[(size_t)(tid + 256) * NF];

    const float4* src = (const float4*)Xb;
    float4* dst = (float4*)Xs;
    float4 v0 = src[tid];
    float4 v1 = src[tid + 256];
    float4 v2 = src[tid + 512];
    float4 v3 = src[tid + 768];
    float4 v4 = src[tid + 1024];
    float4 v5 = src[tid + 1280];
    const bool tl = tid < (TILE4 - 1536);   // 128 tail float4s
    float4 v6;
    if (tl) v6 = src[tid + 1536];

    // symmetrized score matrix (A = attn_w^T; A_ij + A_ji is transpose-invariant)
    if (tid < NF * NF) {
        const int i = tid / NF, j = tid % NF;
        Ss[tid] = (i == j) ? attn_w[tid]
                           : attn_w[i * NF + j] + attn_w[j * NF + i];
    }

    dst[tid]        = v0;
    dst[tid + 256]  = v1;
    dst[tid + 512]  = v2;
    dst[tid + 768]  = v3;
    dst[tid + 1024] = v4;
    dst[tid + 1280] = v5;
    if (tl) dst[tid + 1536] = v6;
    __syncthreads();   // (1)

    // pull both positions' rows into registers (13 coprime 32 -> conflict-free)
    float x0[NF], x1[NF];
    {
        const float* p0 = &Xs[tid * NF];
        const float* p1 = &Xs[(tid + 256) * NF];
        #pragma unroll
        for (int i = 0; i < NF; ++i) { x0[i] = p0[i]; x1[i] = p1[i]; }
    }

    // s = sum_i A_ii x_i^2 + sum_{i<j} (A_ij+A_ji) x_i x_j
    float s0 = 0.0f, s1 = 0.0f;
    #pragma unroll
    for (int i = 0; i < NF; ++i) {
        const float di = Ss[i * NF + i];
        s0 = fmaf(di * x0[i], x0[i], s0);
        s1 = fmaf(di * x1[i], x1[i], s1);
        #pragma unroll
        for (int j = i + 1; j < NF; ++j) {
            const float c = Ss[i * NF + j];
            s0 = fmaf(c * x0[i], x0[j], s0);
            s1 = fmaf(c * x1[i], x1[j], s1);
        }
    }

    // logits bounded by tanh; masked -> exp(-1e5) = 0. No max subtraction.
    const float e0 = __expf(tanhf(s0) + (m0 - 1.0f) * NEG_BIG);
    const float e1 = __expf(tanhf(s1) + (m1 - 1.0f) * NEG_BIG);

    float sum = e0 + e1;
    #pragma unroll
    for (int o = 16; o; o >>= 1) sum += __shfl_xor_sync(0xffffffffu, sum, o);
    if (lane == 0) sred[warp] = sum;
    __syncthreads();   // (2)
    float bsum = sred[0];
    #pragma unroll
    for (int w = 1; w < 8; ++w) bsum += sred[w];
    const float inv = 1.0f / bsum;
    const float w0 = e0 * inv, w1 = e1 * inv;

    // weighted sum H = sum_l W_l x_l  (x rows still in registers)
    #pragma unroll
    for (int i = 0; i < NF; ++i) {
        float v = w0 * x0[i] + w1 * x1[i];
        #pragma unroll
        for (int o = 16; o; o >>= 1) v += __shfl_xor_sync(0xffffffffu, v, o);
        if (lane == 0) red[warp * NF + i] = v;
    }
    __syncthreads();   // (3)
    if (tid < NF) {
        float h = 0.0f;
        #pragma unroll
        for (int w = 0; w < 8; ++w) h += red[w * NF + tid];
        g_H[(size_t)job * NF + tid] = h;
    }
}

// ---------------------------------------------------------------------------
// Kernel 2: d[bm] = ||H1 - H2||^2   (g_H is L2-resident)
// ---------------------------------------------------------------------------
__global__ __launch_bounds__(256) void d_kernel()
{
    const int bm = blockIdx.x * 256 + threadIdx.x;
    if (bm < NN * MM) {
        const float* h1 = g_H + (size_t)bm * NF;
        const float* h2 = g_H + (size_t)(HALF + bm) * NF;
        float d = 0.0f;
        #pragma unroll
        for (int i = 0; i < NF; ++i) {
            const float t = h1[i] - h2[i];
            d += t * t;
        }
        g_d[bm] = d;
    }
}

// ---------------------------------------------------------------------------
// Kernel 3: out[n,i] = sum_j d[n,j] * layer_w[i,j] + layer_b[i]
// grid = 1128 blocks (one column each), 128 threads, float4 loads.
// ---------------------------------------------------------------------------
__global__ __launch_bounds__(128) void fc_kernel(
    const float* __restrict__ layer_w,
    const float* __restrict__ layer_b,
    float* __restrict__ out)
{
    const int i    = blockIdx.x;
    const int tid  = threadIdx.x;
    const int warp = tid >> 5;
    const int lane = tid & 31;

    const float4* wr = (const float4*)(layer_w + (size_t)i * MM);
    const float4* d0 = (const float4*)(g_d);
    const float4* d1 = (const float4*)(g_d + MM);
    const float4* d2 = (const float4*)(g_d + 2 * MM);
    const float4* d3 = (const float4*)(g_d + 3 * MM);

    float a0 = 0.f, a1 = 0.f, a2 = 0.f, a3 = 0.f;
    for (int j = tid; j < MM / 4; j += 128) {
        const float4 w = wr[j];
        float4 v;
        v = d0[j]; a0 += w.x * v.x + w.y * v.y + w.z * v.z + w.w * v.w;
        v = d1[j]; a1 += w.x * v.x + w.y * v.y + w.z * v.z + w.w * v.w;
        v = d2[j]; a2 += w.x * v.x + w.y * v.y + w.z * v.z + w.w * v.w;
        v = d3[j]; a3 += w.x * v.x + w.y * v.y + w.z * v.z + w.w * v.w;
    }
    #pragma unroll
    for (int o = 16; o; o >>= 1) {
        a0 += __shfl_xor_sync(0xffffffffu, a0, o);
        a1 += __shfl_xor_sync(0xffffffffu, a1, o);
        a2 += __shfl_xor_sync(0xffffffffu, a2, o);
        a3 += __shfl_xor_sync(0xffffffffu, a3, o);
    }
    __shared__ float r[4][NN];
    if (lane == 0) { r[warp][0] = a0; r[warp][1] = a1; r[warp][2] = a2; r[warp][3] = a3; }
    __syncthreads();
    if (tid == 0) {
        const float b = layer_b[i];
        #pragma unroll
        for (int n = 0; n < NN; ++n)
            out[n * MM + i] = r[0][n] + r[1][n] + r[2][n] + r[3][n] + b;
    }
}

extern "C" void kernel_launch(void* const* d_in, const int* in_sizes, int n_in,
                              void* d_out, int out_size)
{
    const float* X1      = (const float*)d_in[0];
    const float* X2      = (const float*)d_in[1];
    const float* M1      = (const float*)d_in[2];
    const float* M2      = (const float*)d_in[3];
    const float* attn_w  = (const float*)d_in[4];
    const float* layer_w = (const float*)d_in[5];
    const float* layer_b = (const float*)d_in[6];
    float* out = (float*)d_out;

    pool_kernel<<<JOBS, 256>>>(X1, X2, M1, M2, attn_w);
    d_kernel<<<(NN * MM + 255) / 256, 256>>>();
    fc_kernel<<<MM, 128>>>(layer_w, layer_b, out);
}